// round 6
// baseline (speedup 1.0000x reference)
#include <cuda_runtime.h>
#include <cuda_bf16.h>

typedef unsigned long long u64;

// ---- packed f32x2 helpers (sm_100a; ptxas never emits FFMA2 from C++) ----
__device__ __forceinline__ u64 pack2_dup(float v) {
    u64 r; asm("mov.b64 %0, {%1, %1};" : "=l"(r) : "f"(v)); return r;
}
__device__ __forceinline__ u64 pack2(float lo, float hi) {
    u64 r; asm("mov.b64 %0, {%1, %2};" : "=l"(r) : "f"(lo), "f"(hi)); return r;
}
__device__ __forceinline__ void fma2(u64 &d, u64 a, u64 b) {
    asm("fma.rn.f32x2 %0, %1, %2, %0;" : "+l"(d) : "l"(a), "l"(b));
}
__device__ __forceinline__ void unpack2(u64 v, float &lo, float &hi) {
    asm("mov.b64 {%0, %1}, %2;" : "=f"(lo), "=f"(hi) : "l"(v));
}

// ---- problem geometry ----
// x: [4,20,20,40,40,8]  k: [3,3,3,3,8,16]  out: [4,18,18,38,38,16], VALID, stride 1
constexpr int Tt = 20, Zz = 20, Hh = 40, Ww = 40, CI = 8;
constexpr int OT = 18, OZ = 18, OH = 38, OW = 38, CO = 16;
constexpr int XS_H = Ww * CI;        // 320
constexpr int XS_Z = Hh * XS_H;      // 12,800
constexpr int XS_T = Zz * XS_Z;      // 256,000
constexpr int XS_B = Tt * XS_T;      // 5,120,000

// SMEM x slab: 12 H-rows x 40 w, padded 10 floats per w (8 data + 2 pad)
constexpr int SXW    = 10;
constexpr int SXROW  = Ww * SXW;     // 400 floats per row
constexpr int SXROWS = 12;           // 10 output rows + 2 halo
constexpr int TPB    = 96;           // 5 ti-rows x 19 wp (95 active)
constexpr int NHB    = 4;            // h-blocks per (b,t,z): hp0 in {0,5,10,15}
constexpr int NBLK   = 4 * OT * OZ * NHB;   // 5184

__global__ void __launch_bounds__(TPB, 3) conv4d_kernel(
    const float* __restrict__ x, const float* __restrict__ wgt,
    const float* __restrict__ bias, float* __restrict__ out)
{
    __shared__ __align__(16) float sx[SXROWS * SXROW];   // 19,200 B static

    int bid  = blockIdx.x;
    int hb   = bid & 3; int rest = bid >> 2;
    int z    = rest % OZ; rest /= OZ;
    int t    = rest % OT;
    int b    = rest / OT;
    const int hp0 = hb * 5;

    const int tid = threadIdx.x;
    int ti = tid / 19;                 // 0..5 (tid 95 -> 5)
    const int wp = tid - ti * 19;
    if (ti > 4) ti = 4;                // clamp smem window for idle lane 95
    const int hpr = hp0 + ti;
    const bool active = (tid < 95) && (hpr < 19);
    const int hp = (hpr < 19) ? hpr : 18;   // clamp for hb=3 tail
    const int w0 = wp * 2, h0 = hp * 2;

    // 2x2 output points x 16 couts as 8 f32x2 accumulators each, bias-init.
    u64 acc[4][8];
    #pragma unroll
    for (int cp = 0; cp < 8; cp++) {
        u64 bv = pack2(bias[cp * 2], bias[cp * 2 + 1]);
        #pragma unroll
        for (int p = 0; p < 4; p++) acc[p][cp] = bv;
    }

    #pragma unroll 1
    for (int kt = 0; kt < 3; kt++) {
        #pragma unroll 1
        for (int kz = 0; kz < 3; kz++) {
            __syncthreads();    // prior slab reads complete
            // Cooperatively stage 12 H-rows of plane (b, t+kt, z+kz):
            // 1920 float2, coalesced LDG, padded STS. 20 iters/thread.
            const float* xpl = x + b * XS_B + (t + kt) * XS_T + (z + kz) * XS_Z;
            #pragma unroll
            for (int it = 0; it < (SXROWS * Ww * 4) / TPB; it++) {
                int i = tid + it * TPB;
                int r = i / (Ww * 4);
                int c = i - r * (Ww * 4);        // float2 index within row
                int row = 2 * hp0 + r; if (row > Hh - 1) row = Hh - 1;
                float2 v = *(const float2*)(xpl + row * XS_H + c * 2);
                *(float2*)(sx + r * SXROW + (c >> 2) * SXW + (c & 3) * 2) = v;
            }
            __syncthreads();

            #pragma unroll 1
            for (int kh = 0; kh < 3; kh++) {
                // Stage thread's 2-row x 32-float x window from SMEM.
                float xr[2][32];
                const float* xr0 = sx + (2 * ti + kh) * SXROW + wp * (2 * SXW);
                #pragma unroll
                for (int ph = 0; ph < 2; ph++)
                    #pragma unroll
                    for (int blk = 0; blk < 4; blk++)
                        #pragma unroll
                        for (int cp = 0; cp < 4; cp++)
                            *(float2*)&xr[ph][blk * 8 + cp * 2] =
                                *(const float2*)(xr0 + ph * SXROW + blk * SXW + cp * 2);

                // Weights straight from gmem: warp-uniform LDG -> 1 wf/instr,
                // 41.5 KB stays L1-resident.
                const float* wt = wgt + ((kt * 3 + kz) * 3 + kh) * 3 * (CI * CO);
                #pragma unroll
                for (int kw = 0; kw < 3; kw++) {
                    #pragma unroll
                    for (int ci = 0; ci < CI; ci++) {
                        const ulonglong2* wq =
                            (const ulonglong2*)(wt + kw * (CI * CO) + ci * CO);
                        ulonglong2 q0 = wq[0];
                        ulonglong2 q1 = wq[1];
                        ulonglong2 q2 = wq[2];
                        ulonglong2 q3 = wq[3];
                        #pragma unroll
                        for (int ph = 0; ph < 2; ph++)
                            #pragma unroll
                            for (int pw = 0; pw < 2; pw++) {
                                const int p = ph * 2 + pw;
                                u64 xx = pack2_dup(xr[ph][(kw + pw) * 8 + ci]);
                                fma2(acc[p][0], xx, q0.x);
                                fma2(acc[p][1], xx, q0.y);
                                fma2(acc[p][2], xx, q1.x);
                                fma2(acc[p][3], xx, q1.y);
                                fma2(acc[p][4], xx, q2.x);
                                fma2(acc[p][5], xx, q2.y);
                                fma2(acc[p][6], xx, q3.x);
                                fma2(acc[p][7], xx, q3.y);
                            }
                    }
                }
            }
        }
    }

    if (active) {
        #pragma unroll
        for (int ph = 0; ph < 2; ph++)
            #pragma unroll
            for (int pw = 0; pw < 2; pw++) {
                const int p = ph * 2 + pw;
                float* o = out + (((((b * OT + t) * OZ + z) * OH + (h0 + ph)) * OW
                                   + (w0 + pw)) * CO);
                #pragma unroll
                for (int cp = 0; cp < 8; cp += 2) {
                    float4 v;
                    unpack2(acc[p][cp],     v.x, v.y);
                    unpack2(acc[p][cp + 1], v.z, v.w);
                    *(float4*)(o + cp * 2) = v;
                }
            }
    }
}

extern "C" void kernel_launch(void* const* d_in, const int* in_sizes, int n_in,
                              void* d_out, int out_size)
{
    const float* x    = (const float*)d_in[0];
    const float* wgt  = (const float*)d_in[1];
    const float* bias = (const float*)d_in[2];
    float* out        = (float*)d_out;
    conv4d_kernel<<<NBLK, TPB>>>(x, wgt, bias, out);
}

// round 7
// speedup vs baseline: 1.3112x; 1.3112x over previous
#include <cuda_runtime.h>
#include <cuda_bf16.h>

typedef unsigned long long u64;

// ---- packed f32x2 helpers (sm_100a; ptxas never emits FFMA2 from C++) ----
__device__ __forceinline__ u64 pack2_dup(float v) {
    u64 r; asm("mov.b64 %0, {%1, %1};" : "=l"(r) : "f"(v)); return r;
}
__device__ __forceinline__ u64 pack2(float lo, float hi) {
    u64 r; asm("mov.b64 %0, {%1, %2};" : "=l"(r) : "f"(lo), "f"(hi)); return r;
}
__device__ __forceinline__ void fma2(u64 &d, u64 a, u64 b) {
    asm("fma.rn.f32x2 %0, %1, %2, %0;" : "+l"(d) : "l"(a), "l"(b));
}
__device__ __forceinline__ void unpack2(u64 v, float &lo, float &hi) {
    asm("mov.b64 {%0, %1}, %2;" : "=f"(lo), "=f"(hi) : "l"(v));
}

// ---- problem geometry ----
// x: [4,20,20,40,40,8]  k: [3,3,3,3,8,16]  out: [4,18,18,38,38,16], VALID, stride 1
constexpr int Tt = 20, Zz = 20, Hh = 40, Ww = 40, CI = 8;
constexpr int Bb = 4;
constexpr int OT = 18, OZ = 18, OH = 38, OW = 38, CO = 16;
constexpr int HP = OH / 2, WP = OW / 2;              // 19 x 19 2x2-point tiles
constexpr int NWORK = Bb * OT * OZ * HP * WP;        // 467,856 threads
// x strides (floats)
constexpr int XS_H = Ww * CI;                        // 320
constexpr int XS_Z = Hh * XS_H;                      // 12,800
constexpr int XS_T = Zz * XS_Z;                      // 256,000
constexpr int XS_B = Tt * XS_T;                      // 5,120,000
constexpr int NWGT = 81 * CI * CO;                   // 10,368 floats = 41.5 KB

constexpr int TPB = 128;                             // 3 CTAs/SM -> 12 warps

// Load one x row window: 32 consecutive floats (4 ci-blocks).
__device__ __forceinline__ void load_row(float (&r)[32], const float* p) {
    #pragma unroll
    for (int i = 0; i < 8; i++) {
        float4 v = *(const float4*)(p + i * 4);
        r[i * 4 + 0] = v.x; r[i * 4 + 1] = v.y;
        r[i * 4 + 2] = v.z; r[i * 4 + 3] = v.w;
    }
}

// FMA body for one (kt,kz,kh) tap-row: lo = x row for ph=0, hi = row for ph=1.
__device__ __forceinline__ void tap_body(
    const float* __restrict__ swt3, const float (&lo)[32], const float (&hi)[32],
    u64 (&acc)[4][8])
{
    #pragma unroll
    for (int kw = 0; kw < 3; kw++) {
        const float* swt = swt3 + kw * (CI * CO);
        #pragma unroll
        for (int ci = 0; ci < CI; ci++) {
            // 16 couts for this (tap, ci): 4 uniform broadcast LDS.128
            const ulonglong2* wq = (const ulonglong2*)(swt + ci * CO);
            ulonglong2 q0 = wq[0];
            ulonglong2 q1 = wq[1];
            ulonglong2 q2 = wq[2];
            ulonglong2 q3 = wq[3];
            #pragma unroll
            for (int ph = 0; ph < 2; ph++) {
                const float (&row)[32] = ph ? hi : lo;
                #pragma unroll
                for (int pw = 0; pw < 2; pw++) {
                    const int p = ph * 2 + pw;
                    u64 xx = pack2_dup(row[(kw + pw) * 8 + ci]);
                    fma2(acc[p][0], xx, q0.x);
                    fma2(acc[p][1], xx, q0.y);
                    fma2(acc[p][2], xx, q1.x);
                    fma2(acc[p][3], xx, q1.y);
                    fma2(acc[p][4], xx, q2.x);
                    fma2(acc[p][5], xx, q2.y);
                    fma2(acc[p][6], xx, q3.x);
                    fma2(acc[p][7], xx, q3.y);
                }
            }
        }
    }
}

__global__ void __launch_bounds__(TPB, 3) conv4d_kernel(
    const float* __restrict__ x, const float* __restrict__ wgt,
    const float* __restrict__ bias, float* __restrict__ out)
{
    // Full weight tensor in SMEM, original [tap][ci][co] layout.
    __shared__ __align__(16) float sw[NWGT];
    {
        const float4* g4 = (const float4*)wgt;
        float4* s4 = (float4*)sw;
        for (int i = threadIdx.x; i < NWGT / 4; i += TPB) s4[i] = g4[i];
    }
    __syncthreads();

    int idx = blockIdx.x * TPB + threadIdx.x;
    const bool active = idx < NWORK;
    int id = active ? idx : 0;     // inactive threads compute garbage in-bounds, skip store
    int wp = id % WP; id /= WP;
    int hp = id % HP; id /= HP;
    int z  = id % OZ; id /= OZ;
    int t  = id % OT;
    int b  = id / OT;
    const int h0 = hp * 2, w0 = wp * 2;

    // 2x2 output points x 16 couts as 8 f32x2 accumulators each, bias-init.
    u64 acc[4][8];
    #pragma unroll
    for (int cp = 0; cp < 8; cp++) {
        u64 bv = pack2(bias[cp * 2], bias[cp * 2 + 1]);
        #pragma unroll
        for (int p = 0; p < 4; p++) acc[p][cp] = bv;
    }

    const float* xb = x + b * XS_B + t * XS_T + z * XS_Z + h0 * XS_H + w0 * CI;

    #pragma unroll 1
    for (int kt = 0; kt < 3; kt++) {
        #pragma unroll 1
        for (int kz = 0; kz < 3; kz++) {
            const float* xp  = xb + kt * XS_T + kz * XS_Z;
            const float* swb = sw + ((kt * 3 + kz) * 3) * 3 * (CI * CO);
            constexpr int TS = 3 * (CI * CO);   // per-kh weight stride

            // Rolling 2-row buffers over kh: 4 unique rows, 4 row-loads
            // (R5 loaded 6). Steady-state live regs identical to R5.
            float ra[32], rb[32];
            load_row(ra, xp);                      // row h0
            load_row(rb, xp + XS_H);               // row h0+1
            tap_body(swb + 0 * TS, ra, rb, acc);   // kh=0: (h0, h0+1)
            load_row(ra, xp + 2 * XS_H);           // row h0+2 (ra dead)
            tap_body(swb + 1 * TS, rb, ra, acc);   // kh=1: (h0+1, h0+2)
            load_row(rb, xp + 3 * XS_H);           // row h0+3 (rb dead)
            tap_body(swb + 2 * TS, ra, rb, acc);   // kh=2: (h0+2, h0+3)
        }
    }

    if (active) {
        #pragma unroll
        for (int ph = 0; ph < 2; ph++)
            #pragma unroll
            for (int pw = 0; pw < 2; pw++) {
                const int p = ph * 2 + pw;
                float* o = out + (((((b * OT + t) * OZ + z) * OH + (h0 + ph)) * OW
                                   + (w0 + pw)) * CO);
                #pragma unroll
                for (int cp = 0; cp < 8; cp += 2) {
                    float4 v;
                    unpack2(acc[p][cp],     v.x, v.y);
                    unpack2(acc[p][cp + 1], v.z, v.w);
                    *(float4*)(o + cp * 2) = v;
                }
            }
    }
}

extern "C" void kernel_launch(void* const* d_in, const int* in_sizes, int n_in,
                              void* d_out, int out_size)
{
    const float* x    = (const float*)d_in[0];
    const float* wgt  = (const float*)d_in[1];
    const float* bias = (const float*)d_in[2];
    float* out        = (float*)d_out;
    const int blocks = (NWORK + TPB - 1) / TPB;
    conv4d_kernel<<<blocks, TPB>>>(x, wgt, bias, out);
}

// round 8
// speedup vs baseline: 1.4106x; 1.0757x over previous
#include <cuda_runtime.h>
#include <cuda_bf16.h>

typedef unsigned long long u64;

// ---- packed f32x2 helpers (sm_100a; ptxas never emits FFMA2 from C++) ----
__device__ __forceinline__ u64 pack2_dup(float v) {
    u64 r; asm("mov.b64 %0, {%1, %1};" : "=l"(r) : "f"(v)); return r;
}
__device__ __forceinline__ u64 pack2(float lo, float hi) {
    u64 r; asm("mov.b64 %0, {%1, %2};" : "=l"(r) : "f"(lo), "f"(hi)); return r;
}
__device__ __forceinline__ void fma2(u64 &d, u64 a, u64 b) {
    asm("fma.rn.f32x2 %0, %1, %2, %0;" : "+l"(d) : "l"(a), "l"(b));
}
__device__ __forceinline__ void unpack2(u64 v, float &lo, float &hi) {
    asm("mov.b64 {%0, %1}, %2;" : "=f"(lo), "=f"(hi) : "l"(v));
}

// ---- problem geometry ----
// x: [4,20,20,40,40,8]  k: [3,3,3,3,8,16]  out: [4,18,18,38,38,16], VALID, stride 1
constexpr int Tt = 20, Zz = 20, Hh = 40, Ww = 40, CI = 8;
constexpr int Bb = 4;
constexpr int OT = 18, OZ = 18, OH = 38, OW = 38, CO = 16;
constexpr int HP = OH / 2, WP = OW / 2;              // 19 x 19 2x2-point tiles
constexpr int NWORK = Bb * OT * OZ * HP * WP;        // 467,856 threads
// x strides (floats)
constexpr int XS_H = Ww * CI;                        // 320
constexpr int XS_Z = Hh * XS_H;                      // 12,800
constexpr int XS_T = Zz * XS_Z;                      // 256,000
constexpr int XS_B = Tt * XS_T;                      // 5,120,000
constexpr int NWGT = 81 * CI * CO;                   // 10,368 floats = 41.5 KB

constexpr int TPB = 128;                             // 4 CTAs/SM -> 16 warps

// Load one x half-row window: 4 blocks x 4 floats of one ci-half.
// Block b's half lives at byte offset b*32 + half*16.
__device__ __forceinline__ void load_half_row(float (&r)[16], const float* p) {
    #pragma unroll
    for (int b = 0; b < 4; b++) {
        float4 v = *(const float4*)(p + b * 8);
        r[b * 4 + 0] = v.x; r[b * 4 + 1] = v.y;
        r[b * 4 + 2] = v.z; r[b * 4 + 3] = v.w;
    }
}

// FMA body for one (kt,kz,kh) tap-row, one ci-half (4 ci values).
// lo = x half-row for ph=0, hi = half-row for ph=1.
__device__ __forceinline__ void tap_half(
    const float* __restrict__ swt3, int half,
    const float (&lo)[16], const float (&hi)[16], u64 (&acc)[4][8])
{
    #pragma unroll
    for (int kw = 0; kw < 3; kw++) {
        const float* swt = swt3 + kw * (CI * CO) + half * 4 * CO;
        #pragma unroll
        for (int c = 0; c < 4; c++) {
            // 16 couts for this (tap, ci): 4 uniform broadcast LDS.128
            const ulonglong2* wq = (const ulonglong2*)(swt + c * CO);
            ulonglong2 q0 = wq[0];
            ulonglong2 q1 = wq[1];
            ulonglong2 q2 = wq[2];
            ulonglong2 q3 = wq[3];
            #pragma unroll
            for (int ph = 0; ph < 2; ph++) {
                const float (&row)[16] = ph ? hi : lo;
                #pragma unroll
                for (int pw = 0; pw < 2; pw++) {
                    const int p = ph * 2 + pw;
                    u64 xx = pack2_dup(row[(kw + pw) * 4 + c]);
                    fma2(acc[p][0], xx, q0.x);
                    fma2(acc[p][1], xx, q0.y);
                    fma2(acc[p][2], xx, q1.x);
                    fma2(acc[p][3], xx, q1.y);
                    fma2(acc[p][4], xx, q2.x);
                    fma2(acc[p][5], xx, q2.y);
                    fma2(acc[p][6], xx, q3.x);
                    fma2(acc[p][7], xx, q3.y);
                }
            }
        }
    }
}

__global__ void __launch_bounds__(TPB, 4) conv4d_kernel(
    const float* __restrict__ x, const float* __restrict__ wgt,
    const float* __restrict__ bias, float* __restrict__ out)
{
    // Full weight tensor in SMEM, original [tap][ci][co] layout.
    __shared__ __align__(16) float sw[NWGT];
    {
        const float4* g4 = (const float4*)wgt;
        float4* s4 = (float4*)sw;
        for (int i = threadIdx.x; i < NWGT / 4; i += TPB) s4[i] = g4[i];
    }
    __syncthreads();

    int idx = blockIdx.x * TPB + threadIdx.x;
    const bool active = idx < NWORK;
    int id = active ? idx : 0;     // inactive threads compute garbage in-bounds, skip store
    int wp = id % WP; id /= WP;
    int hp = id % HP; id /= HP;
    int z  = id % OZ; id /= OZ;
    int t  = id % OT;
    int b  = id / OT;
    const int h0 = hp * 2, w0 = wp * 2;

    const float* xb = x + b * XS_B + t * XS_T + z * XS_Z + h0 * XS_H + w0 * CI;
    float* ob = out + (((((b * OT + t) * OZ + z) * OH + h0) * OW + w0) * CO);

    // 2x2 output points x 16 couts as 8 f32x2 accumulators each, bias-init.
    u64 acc[4][8];
    #pragma unroll
    for (int cp = 0; cp < 8; cp++) {
        u64 bv = pack2(bias[cp * 2], bias[cp * 2 + 1]);
        #pragma unroll
        for (int p = 0; p < 4; p++) acc[p][cp] = bv;
    }

    #pragma unroll 1
    for (int kt = 0; kt < 3; kt++) {
        #pragma unroll 1
        for (int kz = 0; kz < 3; kz++) {
            const float* xp  = xb + kt * XS_T + kz * XS_Z;
            const float* swb = sw + ((kt * 3 + kz) * 3) * 3 * (CI * CO);
            constexpr int TS = 3 * (CI * CO);   // per-kh weight stride

            // ci-split halves: half row buffers (16 floats) keep live regs
            // low enough for 4 CTAs/SM. Rolling 2-row buffers over kh.
            #pragma unroll 1
            for (int half = 0; half < 2; half++) {
                const float* xph = xp + half * 4;
                float ra[16], rb[16];
                load_half_row(ra, xph);                        // row h0
                load_half_row(rb, xph + XS_H);                 // row h0+1
                tap_half(swb + 0 * TS, half, ra, rb, acc);     // kh=0
                load_half_row(ra, xph + 2 * XS_H);             // row h0+2
                tap_half(swb + 1 * TS, half, rb, ra, acc);     // kh=1
                load_half_row(rb, xph + 3 * XS_H);             // row h0+3
                tap_half(swb + 2 * TS, half, ra, rb, acc);     // kh=2
            }
        }
    }

    if (active) {
        #pragma unroll
        for (int ph = 0; ph < 2; ph++)
            #pragma unroll
            for (int pw = 0; pw < 2; pw++) {
                const int p = ph * 2 + pw;
                float* o = ob + (ph * OW + pw) * CO;
                #pragma unroll
                for (int cp = 0; cp < 8; cp += 2) {
                    float4 v;
                    unpack2(acc[p][cp],     v.x, v.y);
                    unpack2(acc[p][cp + 1], v.z, v.w);
                    *(float4*)(o + cp * 2) = v;
                }
            }
    }
}

extern "C" void kernel_launch(void* const* d_in, const int* in_sizes, int n_in,
                              void* d_out, int out_size)
{
    const float* x    = (const float*)d_in[0];
    const float* wgt  = (const float*)d_in[1];
    const float* bias = (const float*)d_in[2];
    float* out        = (float*)d_out;
    const int blocks = (NWORK + TPB - 1) / TPB;
    conv4d_kernel<<<blocks, TPB>>>(x, wgt, bias, out);
}